// round 2
// baseline (speedup 1.0000x reference)
#include <cuda_runtime.h>

#define NT 256
#define PJ_STRIDE 68
#define ATT_STRIDE 52

// shared layout (float offsets)
#define OFF_X    0        // 51*32 = 1632
#define OFF_H    1632     // 51*32 = 1632
#define OFF_PI   3264     // 51*64 = 3264 (also emb hidden scratch + final MLP scratch)
#define OFF_PJ   6528     // 51*68 = 3468
#define OFF_ATT  9996     // 51*52 = 2652
#define OFF_W    12648    // 4288 weight staging
#define OFF_ST   16936    // 768 state row
#define OFF_O    17704    // 64
#define SMEM_FLOATS 17768

template<bool FULL>
__device__ __forceinline__ void gat_layer(
    float* sm, const float* __restrict__ Xin, float* __restrict__ Hout,
    const float* __restrict__ gw0, const float* __restrict__ gb0,
    const float* __restrict__ gw1, const float* __restrict__ gb1,
    int tid, int wid, int lane)
{
    float* sPi  = sm + OFF_PI;
    float* sPj  = sm + OFF_PJ;
    float* sAtt = sm + OFF_ATT;
    float* sW   = sm + OFF_W;

    // ---- stage weights: gw0 (64x64) -> sW[0..4095], b0 -> 4096, w1 -> 4160, b1 -> 4224
    {
        float4* dst = (float4*)sW;
        const float4* src = (const float4*)gw0;
        for (int i = tid; i < 1024; i += NT) dst[i] = src[i];
        if (tid < 64)            sW[4096 + tid]        = gb0[tid];
        else if (tid < 128)      sW[4160 + (tid - 64)] = gw1[tid - 64];
        else if (tid == 128)     sW[4224]              = gb1[0];
    }
    __syncthreads();

    // ---- P phase: Pi[n][c] = Xin[n] . w0_top[:,c] + b0[c] ; Pj[n][c] = Xin[n] . w0_bot[:,c]
    if (FULL) {
        for (int idx = tid; idx < 51 * 64; idx += NT) {
            int n = idx >> 6, c = idx & 63;
            const float* xr = Xin + n * 32;
            float accI = sW[4096 + c];
            float accJ = 0.f;
            #pragma unroll
            for (int f = 0; f < 32; f++) {
                float xv = xr[f];
                accI = fmaf(xv, sW[f * 64 + c], accI);
                accJ = fmaf(xv, sW[(32 + f) * 64 + c], accJ);
            }
            sPi[n * 64 + c] = accI;
            sPj[n * PJ_STRIDE + c] = accJ;
        }
    } else {
        for (int idx = tid; idx < 51 * 64; idx += NT) {
            int n = idx >> 6, c = idx & 63;
            const float* xr = Xin + n * 32;
            float accJ = 0.f;
            #pragma unroll
            for (int f = 0; f < 32; f++)
                accJ = fmaf(xr[f], sW[(32 + f) * 64 + c], accJ);
            sPj[n * PJ_STRIDE + c] = accJ;
        }
        if (tid < 64) {      // Pi only for row 0
            float accI = sW[4096 + tid];
            #pragma unroll
            for (int f = 0; f < 32; f++)
                accI = fmaf(Xin[f], sW[f * 64 + tid], accI);
            sPi[tid] = accI;
        }
    }
    __syncthreads();

    const int NR = FULL ? 51 : 1;

    // ---- pair phase + in-warp masked softmax. warp w handles rows w, w+8, ...
    for (int i = wid; i < NR; i += 8) {
        int jb  = lane + 32;
        int jbc = jb < 51 ? jb : 50;       // clamp keeps LDS conflict-free (broadcast merge)
        const float4* piv = (const float4*)(sPi + i * 64);
        const float4* w1v = (const float4*)(sW + 4160);
        const float4* pav = (const float4*)(sPj + lane * PJ_STRIDE);
        const float4* pbv = (const float4*)(sPj + jbc * PJ_STRIDE);
        float accA = 0.f, accB = 0.f;
        #pragma unroll
        for (int c4 = 0; c4 < 16; c4++) {
            float4 pi = piv[c4];
            float4 w1 = w1v[c4];
            float4 pa = pav[c4];
            float4 pb = pbv[c4];
            accA = fmaf(fmaxf(pi.x + pa.x, 0.f), w1.x, accA);
            accA = fmaf(fmaxf(pi.y + pa.y, 0.f), w1.y, accA);
            accA = fmaf(fmaxf(pi.z + pa.z, 0.f), w1.z, accA);
            accA = fmaf(fmaxf(pi.w + pa.w, 0.f), w1.w, accA);
            accB = fmaf(fmaxf(pi.x + pb.x, 0.f), w1.x, accB);
            accB = fmaf(fmaxf(pi.y + pb.y, 0.f), w1.y, accB);
            accB = fmaf(fmaxf(pi.z + pb.z, 0.f), w1.z, accB);
            accB = fmaf(fmaxf(pi.w + pb.w, 0.f), w1.w, accB);
        }
        float b1v = sW[4224];
        float Aa = accA + b1v;
        float Ab = accB + b1v;
        float ea = Aa > 0.f ? Aa : 0.04f * Aa;   // leaky relu
        float eb = Ab > 0.f ? Ab : 0.04f * Ab;
        bool va = (i == 0) || (lane != 0);       // adj mask: rows >=1 exclude j==0
        bool vb = jb < 51;
        float m = fmaxf(va ? ea : -3.0e38f, vb ? eb : -3.0e38f);
        #pragma unroll
        for (int off = 16; off > 0; off >>= 1)
            m = fmaxf(m, __shfl_xor_sync(0xffffffffu, m, off));
        float pa = va ? __expf(ea - m) : 0.f;
        float pb = vb ? __expf(eb - m) : 0.f;
        float s = pa + pb;
        #pragma unroll
        for (int off = 16; off > 0; off >>= 1)
            s += __shfl_xor_sync(0xffffffffu, s, off);
        float inv = 1.0f / s;
        sAtt[i * ATT_STRIDE + lane] = pa * inv;
        if (vb) sAtt[i * ATT_STRIDE + jb] = pb * inv;
    }
    __syncthreads();

    // ---- H = att @ Xin (warp per row, lane per feature)
    for (int i = wid; i < NR; i += 8) {
        const float* ar = sAtt + i * ATT_STRIDE;
        const float4* a4 = (const float4*)ar;
        float acc = 0.f;
        #pragma unroll
        for (int j4 = 0; j4 < 12; j4++) {
            float4 a = a4[j4];
            acc = fmaf(a.x, Xin[(j4 * 4 + 0) * 32 + lane], acc);
            acc = fmaf(a.y, Xin[(j4 * 4 + 1) * 32 + lane], acc);
            acc = fmaf(a.z, Xin[(j4 * 4 + 2) * 32 + lane], acc);
            acc = fmaf(a.w, Xin[(j4 * 4 + 3) * 32 + lane], acc);
        }
        acc = fmaf(ar[48], Xin[48 * 32 + lane], acc);
        acc = fmaf(ar[49], Xin[49 * 32 + lane], acc);
        acc = fmaf(ar[50], Xin[50 * 32 + lane], acc);
        Hout[i * 32 + lane] = acc;
    }
    __syncthreads();
}

__global__ void __launch_bounds__(NT, 2) value_net_kernel(
    const float* __restrict__ state,
    const float* __restrict__ wr_w0, const float* __restrict__ wr_b0,
    const float* __restrict__ wr_w1, const float* __restrict__ wr_b1,
    const float* __restrict__ wh_w0, const float* __restrict__ wh_b0,
    const float* __restrict__ wh_w1, const float* __restrict__ wh_b1,
    const float* __restrict__ g0_w0, const float* __restrict__ g0_b0,
    const float* __restrict__ g0_w1, const float* __restrict__ g0_b1,
    const float* __restrict__ g1_w0, const float* __restrict__ g1_b0,
    const float* __restrict__ g1_w1, const float* __restrict__ g1_b1,
    const float* __restrict__ v_w0, const float* __restrict__ v_b0,
    const float* __restrict__ v_w1, const float* __restrict__ v_b1,
    const float* __restrict__ v_w2, const float* __restrict__ v_b2,
    float* __restrict__ out)
{
    extern __shared__ float sm[];
    float* sX  = sm + OFF_X;
    float* sH  = sm + OFF_H;
    float* sPi = sm + OFF_PI;   // doubles as embedding hidden + final MLP scratch
    float* sW  = sm + OFF_W;
    float* sSt = sm + OFF_ST;
    float* sO  = sm + OFF_O;

    const int tid = threadIdx.x;
    const int wid = tid >> 5;
    const int lane = tid & 31;
    const int b = blockIdx.x;

    // ---- stage state row (50x15) and embedding MLP1 weights
    const float* stb = state + b * 750;
    for (int i = tid; i < 750; i += NT) sSt[i] = stb[i];
    for (int i = tid; i < 384; i += NT) sW[i] = wh_w0[i];          // (6,64)
    for (int i = tid; i < 576; i += NT) sW[448 + i] = wr_w0[i];    // (9,64)
    if (tid < 64)       sW[384 + tid]          = wh_b0[tid];
    else if (tid < 128) sW[1024 + (tid - 64)]  = wr_b0[tid - 64];
    __syncthreads();

    // ---- embedding MLP layer 1: hidden in sPi
    for (int idx = tid; idx < 3200; idx += NT) {
        int n = idx >> 6, c = idx & 63;
        const float* hr = sSt + n * 15 + 9;
        float acc = sW[384 + c];
        #pragma unroll
        for (int f = 0; f < 6; f++) acc = fmaf(hr[f], sW[f * 64 + c], acc);
        sPi[idx] = fmaxf(acc, 0.f);
    }
    if (tid < 64) {   // robot hidden
        float acc = sW[1024 + tid];
        #pragma unroll
        for (int f = 0; f < 9; f++) acc = fmaf(sSt[f], sW[448 + f * 64 + tid], acc);
        sPi[3200 + tid] = fmaxf(acc, 0.f);
    }
    __syncthreads();

    // ---- stage embedding MLP2 weights
    for (int i = tid; i < 2048; i += NT) sW[i] = wh_w1[i];           // (64,32)
    for (int i = tid; i < 2048; i += NT) sW[2080 + i] = wr_w1[i];    // (64,32)
    if (tid < 32)      sW[2048 + tid]         = wh_b1[tid];
    else if (tid < 64) sW[4128 + (tid - 32)]  = wr_b1[tid - 32];
    __syncthreads();

    // ---- embedding MLP layer 2 -> X (51 x 32)
    for (int idx = tid; idx < 1600; idx += NT) {
        int n = idx >> 5, f2 = idx & 31;
        const float* hidr = sPi + n * 64;
        float acc = sW[2048 + f2];
        #pragma unroll 16
        for (int c = 0; c < 64; c++) acc = fmaf(hidr[c], sW[c * 32 + f2], acc);
        sX[(n + 1) * 32 + f2] = fmaxf(acc, 0.f);
    }
    if (tid < 32) {   // robot embedding -> X[0]
        float acc = sW[4128 + tid];
        #pragma unroll 16
        for (int c = 0; c < 64; c++) acc = fmaf(sPi[3200 + c], sW[2080 + c * 32 + tid], acc);
        sX[tid] = fmaxf(acc, 0.f);
    }
    __syncthreads();

    // ---- GAT layer 1 (full), GAT layer 2 (row 0 only — output uses node 0 only)
    gat_layer<true >(sm, sX, sH, g0_w0, g0_b0, g0_w1, g0_b1, tid, wid, lane);
    gat_layer<false>(sm, sH, sO, g1_w0, g1_b0, g1_w1, g1_b1, tid, wid, lane);

    // ---- combine: out0 = H1[0] + H2[0] + X[0]
    if (tid < 32) sO[tid] = sO[tid] + sH[tid] + sX[tid];
    __syncthreads();

    // ---- value MLP: 32 -> 150 -> 100 -> 1, relu each (weights via L2/__ldg)
    float* h1 = sPi;         // 150
    float* h2 = sPi + 256;   // 100
    for (int c = tid; c < 150; c += NT) {
        float acc = __ldg(v_b0 + c);
        #pragma unroll 8
        for (int f = 0; f < 32; f++) acc = fmaf(sO[f], __ldg(v_w0 + f * 150 + c), acc);
        h1[c] = fmaxf(acc, 0.f);
    }
    __syncthreads();
    for (int c = tid; c < 100; c += NT) {
        float acc = __ldg(v_b1 + c);
        #pragma unroll 10
        for (int f = 0; f < 150; f++) acc = fmaf(h1[f], __ldg(v_w1 + f * 100 + c), acc);
        h2[c] = fmaxf(acc, 0.f);
    }
    __syncthreads();
    if (tid < 32) {
        float acc = 0.f;
        #pragma unroll
        for (int f = lane; f < 100; f += 32) acc = fmaf(h2[f], __ldg(v_w2 + f), acc);
        #pragma unroll
        for (int off = 16; off > 0; off >>= 1)
            acc += __shfl_xor_sync(0xffffffffu, acc, off);
        if (lane == 0) out[b] = fmaxf(acc + __ldg(v_b2), 0.f);
    }
}

extern "C" void kernel_launch(void* const* d_in, const int* in_sizes, int n_in,
                              void* d_out, int out_size)
{
    const float* state = (const float*)d_in[0];
    // d_in[1] = dropout (unused)
    const float* wr_w0 = (const float*)d_in[2];
    const float* wr_b0 = (const float*)d_in[3];
    const float* wr_w1 = (const float*)d_in[4];
    const float* wr_b1 = (const float*)d_in[5];
    const float* wh_w0 = (const float*)d_in[6];
    const float* wh_b0 = (const float*)d_in[7];
    const float* wh_w1 = (const float*)d_in[8];
    const float* wh_b1 = (const float*)d_in[9];
    const float* g0_w0 = (const float*)d_in[10];
    const float* g0_b0 = (const float*)d_in[11];
    const float* g0_w1 = (const float*)d_in[12];
    const float* g0_b1 = (const float*)d_in[13];
    const float* g1_w0 = (const float*)d_in[14];
    const float* g1_b0 = (const float*)d_in[15];
    const float* g1_w1 = (const float*)d_in[16];
    const float* g1_b1 = (const float*)d_in[17];
    const float* v_w0  = (const float*)d_in[18];
    const float* v_b0  = (const float*)d_in[19];
    const float* v_w1  = (const float*)d_in[20];
    const float* v_b1  = (const float*)d_in[21];
    const float* v_w2  = (const float*)d_in[22];
    const float* v_b2  = (const float*)d_in[23];
    float* out = (float*)d_out;

    int B = in_sizes[0] / 750;
    size_t smem = SMEM_FLOATS * sizeof(float);
    cudaFuncSetAttribute(value_net_kernel,
                         cudaFuncAttributeMaxDynamicSharedMemorySize, (int)smem);
    value_net_kernel<<<B, NT, smem>>>(
        state,
        wr_w0, wr_b0, wr_w1, wr_b1,
        wh_w0, wh_b0, wh_w1, wh_b1,
        g0_w0, g0_b0, g0_w1, g0_b1,
        g1_w0, g1_b0, g1_w1, g1_b1,
        v_w0, v_b0, v_w1, v_b1, v_w2, v_b2,
        out);
}